// round 4
// baseline (speedup 1.0000x reference)
#include <cuda_runtime.h>
#include <cstdint>

#define HID 1024
#define SEQ 1024
#define NB  4
#define NH  16
#define DH  64

__device__ float g_qkv[6][NB * SEQ * HID];

struct QKVArgs {
    const float* x[2];
    const float* w[6];
    const float* b[6];
};

__device__ __forceinline__ uint32_t f2tf(float x) {
    uint32_t t;
    asm("cvt.rna.tf32.f32 %0, %1;" : "=r"(t) : "f"(x));
    return t;
}

__device__ __forceinline__ void mma_tf32(float* c, const uint32_t* a, const uint32_t* b) {
    asm volatile(
        "mma.sync.aligned.m16n8k8.row.col.f32.tf32.tf32.f32 "
        "{%0,%1,%2,%3}, {%4,%5,%6,%7}, {%8,%9}, {%0,%1,%2,%3};\n"
        : "+f"(c[0]), "+f"(c[1]), "+f"(c[2]), "+f"(c[3])
        : "r"(a[0]), "r"(a[1]), "r"(a[2]), "r"(a[3]), "r"(b[0]), "r"(b[1]));
}

__device__ __forceinline__ float fast_exp(float x) {
    x = fmaxf(x, -80.f);
    float t = x * 1.44269504f;
    float r = rintf(t);
    float y = (t - r) * 0.69314718f;
    float p = 8.3333333e-3f;
    p = fmaf(p, y, 4.1666667e-2f);
    p = fmaf(p, y, 1.6666667e-1f);
    p = fmaf(p, y, 5.0e-1f);
    p = fmaf(p, y, 1.0f);
    p = fmaf(p, y, 1.0f);
    return __int_as_float(__float_as_int(p) + (((int)r) << 23));
}

// ---------------------------------------------------------------------------
// QKV projection (unchanged from R3): 128x64x32, 256 thr, double-buffered.
// ---------------------------------------------------------------------------
#define GA_PITCH 36
#define GB_PITCH 72
#define GA_WORDS (128 * GA_PITCH)
#define GB_WORDS (32 * GB_PITCH)
#define GEMM_SMEM ((2 * GA_WORDS + 2 * GB_WORDS) * 4)

__global__ __launch_bounds__(256, 2) void qkv_gemm(QKVArgs args) {
    extern __shared__ uint32_t gsm[];
    uint32_t* As = gsm;
    uint32_t* Bs = gsm + 2 * GA_WORDS;

    const int p = blockIdx.z;
    const float* X    = args.x[p / 3];
    const float* W    = args.w[p];
    const float* bias = args.b[p];
    float* C = g_qkv[p];

    const int tid = threadIdx.x;
    const int wid = tid >> 5;
    const int lane = tid & 31;
    const int ly = lane >> 2;
    const int lx = lane & 3;
    const int wm = (wid & 3) * 32;
    const int wn = (wid >> 2) * 32;
    const int bm = blockIdx.y << 7;
    const int bn = blockIdx.x << 6;

    const int arow = tid >> 3, ac4 = (tid & 7) << 2;
    const int brow = tid >> 4, bc4 = (tid & 15) << 2;

    float4 ra[4], rb[2];

#pragma unroll
    for (int i = 0; i < 4; i++)
        ra[i] = *(const float4*)(X + (size_t)(bm + arow + i * 32) * HID + ac4);
#pragma unroll
    for (int i = 0; i < 2; i++)
        rb[i] = *(const float4*)(W + (size_t)(brow + i * 16) * HID + bn + bc4);
#pragma unroll
    for (int i = 0; i < 4; i++) {
        uint4 t = {f2tf(ra[i].x), f2tf(ra[i].y), f2tf(ra[i].z), f2tf(ra[i].w)};
        *(uint4*)&As[(arow + i * 32) * GA_PITCH + ac4] = t;
    }
#pragma unroll
    for (int i = 0; i < 2; i++) {
        uint4 t = {f2tf(rb[i].x), f2tf(rb[i].y), f2tf(rb[i].z), f2tf(rb[i].w)};
        *(uint4*)&Bs[(brow + i * 16) * GB_PITCH + bc4] = t;
    }
    __syncthreads();

    float acc[2][4][4];
#pragma unroll
    for (int i = 0; i < 2; i++)
#pragma unroll
        for (int j = 0; j < 4; j++)
#pragma unroll
            for (int q = 0; q < 4; q++) acc[i][j][q] = 0.f;

    for (int k0 = 0; k0 < HID; k0 += 32) {
        const int cur = (k0 >> 5) & 1;
        const uint32_t* Ab = As + cur * GA_WORDS;
        const uint32_t* Bb = Bs + cur * GB_WORDS;
        const bool more = (k0 + 32) < HID;

        if (more) {
#pragma unroll
            for (int i = 0; i < 4; i++)
                ra[i] = *(const float4*)(X + (size_t)(bm + arow + i * 32) * HID + k0 + 32 + ac4);
#pragma unroll
            for (int i = 0; i < 2; i++)
                rb[i] = *(const float4*)(W + (size_t)(k0 + 32 + brow + i * 16) * HID + bn + bc4);
        }

#pragma unroll
        for (int ks = 0; ks < 4; ks++) {
            const int kk = ks * 8;
            uint32_t a[2][4], b[4][2];
#pragma unroll
            for (int mi = 0; mi < 2; mi++) {
                int m = wm + mi * 16;
                a[mi][0] = Ab[(m + ly) * GA_PITCH + kk + lx];
                a[mi][1] = Ab[(m + ly + 8) * GA_PITCH + kk + lx];
                a[mi][2] = Ab[(m + ly) * GA_PITCH + kk + lx + 4];
                a[mi][3] = Ab[(m + ly + 8) * GA_PITCH + kk + lx + 4];
            }
#pragma unroll
            for (int ni = 0; ni < 4; ni++) {
                int n = wn + ni * 8;
                b[ni][0] = Bb[(kk + lx) * GB_PITCH + n + ly];
                b[ni][1] = Bb[(kk + lx + 4) * GB_PITCH + n + ly];
            }
#pragma unroll
            for (int mi = 0; mi < 2; mi++)
#pragma unroll
                for (int ni = 0; ni < 4; ni++)
                    mma_tf32(acc[mi][ni], a[mi], b[ni]);
        }

        if (more) {
            uint32_t* An = As + (cur ^ 1) * GA_WORDS;
            uint32_t* Bn = Bs + (cur ^ 1) * GB_WORDS;
#pragma unroll
            for (int i = 0; i < 4; i++) {
                uint4 t = {f2tf(ra[i].x), f2tf(ra[i].y), f2tf(ra[i].z), f2tf(ra[i].w)};
                *(uint4*)&An[(arow + i * 32) * GA_PITCH + ac4] = t;
            }
#pragma unroll
            for (int i = 0; i < 2; i++) {
                uint4 t = {f2tf(rb[i].x), f2tf(rb[i].y), f2tf(rb[i].z), f2tf(rb[i].w)};
                *(uint4*)&Bn[(brow + i * 16) * GB_PITCH + bc4] = t;
            }
        }
        __syncthreads();
    }

#pragma unroll
    for (int mi = 0; mi < 2; mi++) {
#pragma unroll
        for (int ni = 0; ni < 4; ni++) {
            int m = bm + wm + mi * 16 + ly;
            int n = bn + wn + ni * 8 + 2 * lx;
            float b0 = bias[n], b1 = bias[n + 1];
            float2 v0 = {acc[mi][ni][0] + b0, acc[mi][ni][1] + b1};
            float2 v1 = {acc[mi][ni][2] + b0, acc[mi][ni][3] + b1};
            *(float2*)(C + (size_t)m * HID + n) = v0;
            *(float2*)(C + (size_t)(m + 8) * HID + n) = v1;
        }
    }
}

// ---------------------------------------------------------------------------
// Fused cross-attention, 512 threads (16 warps), double-buffered staging.
// Phase1: warps 2(m)x8(n), Q frags hoisted to registers. K pitch 76.
// Phase2: warps 4(k)x4(n), V pitch 72 (conflict-free lx-major frags),
//         4-way smem reduction.
// ---------------------------------------------------------------------------
#define SSC_PITCH 1028
#define Q_PITCH   68
#define KPITCH    76
#define VPITCH    72
#define KV_WORDS  (128 * KPITCH)
#define RED_PITCH 68
#define ATTN_SMEM ((32 * SSC_PITCH + 32 * Q_PITCH + 2 * KV_WORDS) * 4)

__global__ __launch_bounds__(512) void attn_kernel(const float* __restrict__ mask1,
                                                   const float* __restrict__ mask2,
                                                   float* __restrict__ out) {
    extern __shared__ float sm[];
    float*    Ssc = sm;                                   // [32][1028]
    uint32_t* Qs  = (uint32_t*)(sm + 32 * SSC_PITCH);     // [32][68] tf32
    uint32_t* KVs = Qs + 32 * Q_PITCH;                    // 2 x [128][KPITCH]
    float*    red = (float*)KVs;                          // 4 x [32][68] (reused)

    const int qb = blockIdx.x;
    const int h  = blockIdx.y;
    const int b  = blockIdx.z >> 1;
    const int st = blockIdx.z & 1;

    const float* Q    = g_qkv[st * 3];
    const float* K    = st ? g_qkv[1] : g_qkv[4];
    const float* V    = st ? g_qkv[2] : g_qkv[5];
    const float* mask = st ? mask1 : mask2;

    float* probs = out + 8388608 + (size_t)st * 67108864
                 + ((size_t)(b * NH + h) * SEQ + qb * 32) * SEQ;
    float* ctx = out + (size_t)st * 4194304;

    const int tid = threadIdx.x;
    const int wid = tid >> 5;
    const int lane = tid & 31;
    const int ly = lane >> 2;
    const int lx = lane & 3;

    // staging geometry (512 thr): one row per 4 threads, 4 float4 each
    const int srow = tid >> 2;
    const int scol = (tid & 3) << 4;    // element col base (16 elems per thread)

    // Stage Q (tf32): one float4 per thread (32 rows x 16 f4)
    {
        int r = tid >> 4, c4 = (tid & 15) << 2;
        float4 v = *(const float4*)(Q + (size_t)(b * SEQ + qb * 32 + r) * HID + h * DH + c4);
        uint4 t = {f2tf(v.x), f2tf(v.y), f2tf(v.z), f2tf(v.w)};
        *(uint4*)&Qs[r * Q_PITCH + c4] = t;
    }

    float4 stg[4];

    // ---- Phase 1 prologue: K tile 0 ----
#pragma unroll
    for (int j = 0; j < 4; j++)
        stg[j] = *(const float4*)(K + (size_t)(b * SEQ + srow) * HID + h * DH + scol + j * 4);
#pragma unroll
    for (int j = 0; j < 4; j++) {
        uint4 t = {f2tf(stg[j].x), f2tf(stg[j].y), f2tf(stg[j].z), f2tf(stg[j].w)};
        *(uint4*)&KVs[srow * KPITCH + scol + j * 4] = t;
    }
    __syncthreads();

    // Hoisted Q fragments (invariant across K tiles)
    const int wm = (wid & 1) * 16;
    const int wn = (wid >> 1) * 16;
    uint32_t aq[8][4];
#pragma unroll
    for (int ks = 0; ks < 8; ks++) {
        const int kk = ks * 8;
        aq[ks][0] = Qs[(wm + ly) * Q_PITCH + kk + lx];
        aq[ks][1] = Qs[(wm + ly + 8) * Q_PITCH + kk + lx];
        aq[ks][2] = Qs[(wm + ly) * Q_PITCH + kk + lx + 4];
        aq[ks][3] = Qs[(wm + ly + 8) * Q_PITCH + kk + lx + 4];
    }

    for (int kt = 0; kt < 8; kt++) {
        const int cur = kt & 1;
        const uint32_t* KB = KVs + cur * KV_WORDS;
        const bool more = kt < 7;

        if (more) {
#pragma unroll
            for (int j = 0; j < 4; j++)
                stg[j] = *(const float4*)(K + (size_t)(b * SEQ + (kt + 1) * 128 + srow) * HID + h * DH + scol + j * 4);
        }

        float sacc[2][4];
#pragma unroll
        for (int ni = 0; ni < 2; ni++)
#pragma unroll
            for (int q = 0; q < 4; q++) sacc[ni][q] = 0.f;

#pragma unroll
        for (int ks = 0; ks < 8; ks++) {
            const int kk = ks * 8;
            uint32_t bb[2][2];
#pragma unroll
            for (int ni = 0; ni < 2; ni++) {
                int n = wn + ni * 8;
                bb[ni][0] = KB[(n + ly) * KPITCH + kk + lx];
                bb[ni][1] = KB[(n + ly) * KPITCH + kk + lx + 4];
            }
#pragma unroll
            for (int ni = 0; ni < 2; ni++)
                mma_tf32(sacc[ni], aq[ks], bb[ni]);
        }

#pragma unroll
        for (int ni = 0; ni < 2; ni++) {
            int col = kt * 128 + wn + ni * 8 + 2 * lx;
            float mk0 = mask[b * SEQ + col];
            float mk1 = mask[b * SEQ + col + 1];
            int row = wm + ly;
            Ssc[row * SSC_PITCH + col]           = sacc[ni][0] * 0.125f + mk0;
            Ssc[row * SSC_PITCH + col + 1]       = sacc[ni][1] * 0.125f + mk1;
            Ssc[(row + 8) * SSC_PITCH + col]     = sacc[ni][2] * 0.125f + mk0;
            Ssc[(row + 8) * SSC_PITCH + col + 1] = sacc[ni][3] * 0.125f + mk1;
        }

        if (more) {
            uint32_t* KN = KVs + (cur ^ 1) * KV_WORDS;
#pragma unroll
            for (int j = 0; j < 4; j++) {
                uint4 t = {f2tf(stg[j].x), f2tf(stg[j].y), f2tf(stg[j].z), f2tf(stg[j].w)};
                *(uint4*)&KN[srow * KPITCH + scol + j * 4] = t;
            }
        }
        __syncthreads();
    }

    // ---- softmax: 16 warps, rows wid and wid+16 ----
#pragma unroll
    for (int rr = 0; rr < 2; rr++) {
        int r = wid + rr * 16;
        float* row = Ssc + r * SSC_PITCH;
        float m = -1e30f;
        for (int c = lane; c < SEQ; c += 32) m = fmaxf(m, row[c]);
#pragma unroll
        for (int o = 16; o >= 1; o >>= 1) m = fmaxf(m, __shfl_xor_sync(0xffffffffu, m, o));
        float s = 0.f;
        for (int c = lane; c < SEQ; c += 32) {
            float e = fast_exp(row[c] - m);
            row[c] = e;
            s += e;
        }
#pragma unroll
        for (int o = 16; o >= 1; o >>= 1) s += __shfl_xor_sync(0xffffffffu, s, o);
        float inv = 1.f / s;
        for (int c = lane; c < SEQ; c += 32) row[c] *= inv;
    }
    __syncthreads();

    // ---- write probs + convert P to tf32 in place ----
    for (int i = tid; i < 8192; i += 512) {
        int row = i >> 8, c4 = (i & 255) << 2;
        float4 v = *(float4*)&Ssc[row * SSC_PITCH + c4];
        *(float4*)&probs[row * 1024 + c4] = v;
        uint4 t = {f2tf(v.x), f2tf(v.y), f2tf(v.z), f2tf(v.w)};
        *(uint4*)&Ssc[row * SSC_PITCH + c4] = t;
    }

    // ---- Phase 2 prologue: V tile 0 ----
#pragma unroll
    for (int j = 0; j < 4; j++)
        stg[j] = *(const float4*)(V + (size_t)(b * SEQ + srow) * HID + h * DH + scol + j * 4);
#pragma unroll
    for (int j = 0; j < 4; j++) {
        uint4 t = {f2tf(stg[j].x), f2tf(stg[j].y), f2tf(stg[j].z), f2tf(stg[j].w)};
        *(uint4*)&KVs[srow * VPITCH + scol + j * 4] = t;
    }
    __syncthreads();

    const int kgrp = wid & 3;       // owns k-rows kgrp*32..+31 of each tile
    const int ngrp = wid >> 2;      // owns cols ngrp*16..+15

    float cacc[2][2][4];
#pragma unroll
    for (int mi = 0; mi < 2; mi++)
#pragma unroll
        for (int ni = 0; ni < 2; ni++)
#pragma unroll
            for (int q = 0; q < 4; q++) cacc[mi][ni][q] = 0.f;

    const uint32_t* Su = (const uint32_t*)Ssc;

    for (int vt = 0; vt < 8; vt++) {
        const int cur = vt & 1;
        const uint32_t* VB = KVs + cur * KV_WORDS;
        const bool more = vt < 7;

        if (more) {
#pragma unroll
            for (int j = 0; j < 4; j++)
                stg[j] = *(const float4*)(V + (size_t)(b * SEQ + (vt + 1) * 128 + srow) * HID + h * DH + scol + j * 4);
        }

#pragma unroll
        for (int ks = 0; ks < 4; ks++) {
            const int kloc = kgrp * 32 + ks * 8;
            const int kg = vt * 128 + kloc;
            uint32_t a[2][4], bb[2][2];
#pragma unroll
            for (int mi = 0; mi < 2; mi++) {
                int m = mi * 16;
                a[mi][0] = Su[(m + ly) * SSC_PITCH + kg + lx];
                a[mi][1] = Su[(m + ly + 8) * SSC_PITCH + kg + lx];
                a[mi][2] = Su[(m + ly) * SSC_PITCH + kg + lx + 4];
                a[mi][3] = Su[(m + ly + 8) * SSC_PITCH + kg + lx + 4];
            }
#pragma unroll
            for (int ni = 0; ni < 2; ni++) {
                int n = ngrp * 16 + ni * 8;
                bb[ni][0] = VB[(kloc + lx) * VPITCH + n + ly];
                bb[ni][1] = VB[(kloc + lx + 4) * VPITCH + n + ly];
            }
#pragma unroll
            for (int mi = 0; mi < 2; mi++)
#pragma unroll
                for (int ni = 0; ni < 2; ni++)
                    mma_tf32(cacc[mi][ni], a[mi], bb[ni]);
        }

        if (more) {
            uint32_t* VN = KVs + (cur ^ 1) * KV_WORDS;
#pragma unroll
            for (int j = 0; j < 4; j++) {
                uint4 t = {f2tf(stg[j].x), f2tf(stg[j].y), f2tf(stg[j].z), f2tf(stg[j].w)};
                *(uint4*)&VN[srow * VPITCH + scol + j * 4] = t;
            }
        }
        __syncthreads();
    }

    // ---- reduce partial ctx across the 4 k-groups ----
#pragma unroll
    for (int mi = 0; mi < 2; mi++)
#pragma unroll
        for (int ni = 0; ni < 2; ni++)
#pragma unroll
            for (int q = 0; q < 4; q++) {
                int row = mi * 16 + ly + (q >> 1) * 8;
                int col = ngrp * 16 + ni * 8 + 2 * lx + (q & 1);
                red[kgrp * (32 * RED_PITCH) + row * RED_PITCH + col] = cacc[mi][ni][q];
            }
    __syncthreads();

    {
        int row = tid >> 4;
        int col = (tid & 15) << 2;
        float s0 = 0.f, s1 = 0.f, s2 = 0.f, s3 = 0.f;
#pragma unroll
        for (int w = 0; w < 4; w++) {
            const float* rp = red + w * (32 * RED_PITCH) + row * RED_PITCH + col;
            s0 += rp[0]; s1 += rp[1]; s2 += rp[2]; s3 += rp[3];
        }
        float4 v = {s0, s1, s2, s3};
        *(float4*)(ctx + (size_t)(b * SEQ + qb * 32 + row) * HID + h * DH + col) = v;
    }
}

// ---------------------------------------------------------------------------
extern "C" void kernel_launch(void* const* d_in, const int* in_sizes, int n_in,
                              void* d_out, int out_size) {
    (void)in_sizes; (void)n_in; (void)out_size;

    const float* m1 = (const float*)d_in[1];
    const float* m2 = (const float*)d_in[3];

    QKVArgs a;
    a.x[0] = (const float*)d_in[0];
    a.x[1] = (const float*)d_in[2];
    for (int i = 0; i < 6; i++) {
        a.w[i] = (const float*)d_in[4 + 2 * i];
        a.b[i] = (const float*)d_in[5 + 2 * i];
    }

    cudaFuncSetAttribute(qkv_gemm, cudaFuncAttributeMaxDynamicSharedMemorySize,
                         GEMM_SMEM);
    cudaFuncSetAttribute(attn_kernel, cudaFuncAttributeMaxDynamicSharedMemorySize,
                         ATTN_SMEM);

    qkv_gemm<<<dim3(16, 32, 6), 256, GEMM_SMEM>>>(a);
    attn_kernel<<<dim3(32, 16, 8), 512, ATTN_SMEM>>>(m1, m2, (float*)d_out);
}

// round 7
// speedup vs baseline: 1.2643x; 1.2643x over previous
#include <cuda_runtime.h>
#include <cstdint>

#define HID 1024
#define SEQ 1024
#define NB  4
#define NH  16
#define DH  64

// Scratch for q1,k1,v1,q2,k2,v2 : values stored ALREADY tf32-rounded.
__device__ float g_qkv[6][NB * SEQ * HID];

struct QKVArgs {
    const float* x[2];
    const float* w[6];
    const float* b[6];
};

__device__ __forceinline__ uint32_t f2tf(float x) {
    uint32_t t;
    asm("cvt.rna.tf32.f32 %0, %1;" : "=r"(t) : "f"(x));
    return t;
}

__device__ __forceinline__ void mma_tf32(float* c, const uint32_t* a, const uint32_t* b) {
    asm volatile(
        "mma.sync.aligned.m16n8k8.row.col.f32.tf32.tf32.f32 "
        "{%0,%1,%2,%3}, {%4,%5,%6,%7}, {%8,%9}, {%0,%1,%2,%3};\n"
        : "+f"(c[0]), "+f"(c[1]), "+f"(c[2]), "+f"(c[3])
        : "r"(a[0]), "r"(a[1]), "r"(a[2]), "r"(a[3]), "r"(b[0]), "r"(b[1]));
}

#define CP_ASYNC16(saddr, gptr) \
    asm volatile("cp.async.cg.shared.global [%0], [%1], 16;\n" :: "r"(saddr), "l"(gptr))
#define CP_COMMIT() asm volatile("cp.async.commit_group;\n" ::: "memory")
#define CP_WAIT(n)  asm volatile("cp.async.wait_group %0;\n" :: "n"(n) : "memory")

__device__ __forceinline__ float fast_exp(float x) {
    x = fmaxf(x, -80.f);
    float t = x * 1.44269504f;
    float r = rintf(t);
    float y = (t - r) * 0.69314718f;
    float p = 8.3333333e-3f;
    p = fmaf(p, y, 4.1666667e-2f);
    p = fmaf(p, y, 1.6666667e-1f);
    p = fmaf(p, y, 5.0e-1f);
    p = fmaf(p, y, 1.0f);
    p = fmaf(p, y, 1.0f);
    return __int_as_float(__float_as_int(p) + (((int)r) << 23));
}

// ---------------------------------------------------------------------------
// QKV projection: 128x64x32, 256 thr, double-buffered. Epilogue stores the
// result pre-rounded to tf32 (only the attention mmas consume g_qkv).
// ---------------------------------------------------------------------------
#define GA_PITCH 36
#define GB_PITCH 72
#define GA_WORDS (128 * GA_PITCH)
#define GB_WORDS (32 * GB_PITCH)
#define GEMM_SMEM ((2 * GA_WORDS + 2 * GB_WORDS) * 4)

__global__ __launch_bounds__(256, 2) void qkv_gemm(QKVArgs args) {
    extern __shared__ uint32_t gsm[];
    uint32_t* As = gsm;
    uint32_t* Bs = gsm + 2 * GA_WORDS;

    const int p = blockIdx.z;
    const float* X    = args.x[p / 3];
    const float* W    = args.w[p];
    const float* bias = args.b[p];
    float* C = g_qkv[p];

    const int tid = threadIdx.x;
    const int wid = tid >> 5;
    const int lane = tid & 31;
    const int ly = lane >> 2;
    const int lx = lane & 3;
    const int wm = (wid & 3) * 32;
    const int wn = (wid >> 2) * 32;
    const int bm = blockIdx.y << 7;
    const int bn = blockIdx.x << 6;

    const int arow = tid >> 3, ac4 = (tid & 7) << 2;
    const int brow = tid >> 4, bc4 = (tid & 15) << 2;

    float4 ra[4], rb[2];

#pragma unroll
    for (int i = 0; i < 4; i++)
        ra[i] = *(const float4*)(X + (size_t)(bm + arow + i * 32) * HID + ac4);
#pragma unroll
    for (int i = 0; i < 2; i++)
        rb[i] = *(const float4*)(W + (size_t)(brow + i * 16) * HID + bn + bc4);
#pragma unroll
    for (int i = 0; i < 4; i++) {
        uint4 t = {f2tf(ra[i].x), f2tf(ra[i].y), f2tf(ra[i].z), f2tf(ra[i].w)};
        *(uint4*)&As[(arow + i * 32) * GA_PITCH + ac4] = t;
    }
#pragma unroll
    for (int i = 0; i < 2; i++) {
        uint4 t = {f2tf(rb[i].x), f2tf(rb[i].y), f2tf(rb[i].z), f2tf(rb[i].w)};
        *(uint4*)&Bs[(brow + i * 16) * GB_PITCH + bc4] = t;
    }
    __syncthreads();

    float acc[2][4][4];
#pragma unroll
    for (int i = 0; i < 2; i++)
#pragma unroll
        for (int j = 0; j < 4; j++)
#pragma unroll
            for (int q = 0; q < 4; q++) acc[i][j][q] = 0.f;

    for (int k0 = 0; k0 < HID; k0 += 32) {
        const int cur = (k0 >> 5) & 1;
        const uint32_t* Ab = As + cur * GA_WORDS;
        const uint32_t* Bb = Bs + cur * GB_WORDS;
        const bool more = (k0 + 32) < HID;

        if (more) {
#pragma unroll
            for (int i = 0; i < 4; i++)
                ra[i] = *(const float4*)(X + (size_t)(bm + arow + i * 32) * HID + k0 + 32 + ac4);
#pragma unroll
            for (int i = 0; i < 2; i++)
                rb[i] = *(const float4*)(W + (size_t)(k0 + 32 + brow + i * 16) * HID + bn + bc4);
        }

#pragma unroll
        for (int ks = 0; ks < 4; ks++) {
            const int kk = ks * 8;
            uint32_t a[2][4], b[4][2];
#pragma unroll
            for (int mi = 0; mi < 2; mi++) {
                int m = wm + mi * 16;
                a[mi][0] = Ab[(m + ly) * GA_PITCH + kk + lx];
                a[mi][1] = Ab[(m + ly + 8) * GA_PITCH + kk + lx];
                a[mi][2] = Ab[(m + ly) * GA_PITCH + kk + lx + 4];
                a[mi][3] = Ab[(m + ly + 8) * GA_PITCH + kk + lx + 4];
            }
#pragma unroll
            for (int ni = 0; ni < 4; ni++) {
                int n = wn + ni * 8;
                b[ni][0] = Bb[(kk + lx) * GB_PITCH + n + ly];
                b[ni][1] = Bb[(kk + lx + 4) * GB_PITCH + n + ly];
            }
#pragma unroll
            for (int mi = 0; mi < 2; mi++)
#pragma unroll
                for (int ni = 0; ni < 4; ni++)
                    mma_tf32(acc[mi][ni], a[mi], b[ni]);
        }

        if (more) {
            uint32_t* An = As + (cur ^ 1) * GA_WORDS;
            uint32_t* Bn = Bs + (cur ^ 1) * GB_WORDS;
#pragma unroll
            for (int i = 0; i < 4; i++) {
                uint4 t = {f2tf(ra[i].x), f2tf(ra[i].y), f2tf(ra[i].z), f2tf(ra[i].w)};
                *(uint4*)&An[(arow + i * 32) * GA_PITCH + ac4] = t;
            }
#pragma unroll
            for (int i = 0; i < 2; i++) {
                uint4 t = {f2tf(rb[i].x), f2tf(rb[i].y), f2tf(rb[i].z), f2tf(rb[i].w)};
                *(uint4*)&Bn[(brow + i * 16) * GB_PITCH + bc4] = t;
            }
        }
        __syncthreads();
    }

#pragma unroll
    for (int mi = 0; mi < 2; mi++) {
#pragma unroll
        for (int ni = 0; ni < 4; ni++) {
            int m = bm + wm + mi * 16 + ly;
            int n = bn + wn + ni * 8 + 2 * lx;
            float b0 = bias[n], b1 = bias[n + 1];
            float2 v0 = {__uint_as_float(f2tf(acc[mi][ni][0] + b0)),
                         __uint_as_float(f2tf(acc[mi][ni][1] + b1))};
            float2 v1 = {__uint_as_float(f2tf(acc[mi][ni][2] + b0)),
                         __uint_as_float(f2tf(acc[mi][ni][3] + b1))};
            *(float2*)(C + (size_t)m * HID + n) = v0;
            *(float2*)(C + (size_t)(m + 8) * HID + n) = v1;
        }
    }
}

// ---------------------------------------------------------------------------
// Fused cross-attention, 256 threads, cp.async double-buffered staging,
// hoisted Q fragments. g_qkv is pre-tf32 so staging is a raw byte copy.
// ---------------------------------------------------------------------------
#define SSC_PITCH 1028
#define Q_PITCH   68
#define KPITCH    76
#define KV_WORDS  (128 * KPITCH)
#define RED_PITCH 65
#define ATTN_SMEM ((32 * SSC_PITCH + 32 * Q_PITCH + 2 * KV_WORDS) * 4)

__global__ __launch_bounds__(256) void attn_kernel(const float* __restrict__ mask1,
                                                   const float* __restrict__ mask2,
                                                   float* __restrict__ out) {
    extern __shared__ float sm[];
    float*    Ssc = sm;                                   // [32][1028]
    uint32_t* Qs  = (uint32_t*)(sm + 32 * SSC_PITCH);     // [32][68] tf32
    uint32_t* KVs = Qs + 32 * Q_PITCH;                    // 2 x [128][76]
    float*    red = (float*)KVs;                          // 8 x [32][65] (reused)

    const int qb = blockIdx.x;
    const int h  = blockIdx.y;
    const int b  = blockIdx.z >> 1;
    const int st = blockIdx.z & 1;

    const float* Q    = g_qkv[st * 3];
    const float* K    = st ? g_qkv[1] : g_qkv[4];
    const float* V    = st ? g_qkv[2] : g_qkv[5];
    const float* mask = st ? mask1 : mask2;

    float* probs = out + 8388608 + (size_t)st * 67108864
                 + ((size_t)(b * NH + h) * SEQ + qb * 32) * SEQ;
    float* ctx = out + (size_t)st * 4194304;

    const int tid = threadIdx.x;
    const int wid = tid >> 5;
    const int lane = tid & 31;
    const int ly = lane >> 2;
    const int lx = lane & 3;

    // staging: 16 threads per row, 8 rows per thread (rows srow + i*16)
    const int srow = tid >> 4;
    const int sc4 = (tid & 15) << 2;
    const uint32_t kv_base = (uint32_t)__cvta_generic_to_shared(KVs);

    // ---- stage Q (plain copy; already tf32) ----
    for (int i = tid; i < 32 * 16; i += 256) {
        int r = i >> 4, c4 = (i & 15) << 2;
        *(float4*)&Qs[r * Q_PITCH + c4] =
            *(const float4*)(Q + (size_t)(b * SEQ + qb * 32 + r) * HID + h * DH + c4);
    }

    // ---- phase 1 prologue: K tile 0 via cp.async ----
#pragma unroll
    for (int i = 0; i < 8; i++)
        CP_ASYNC16(kv_base + ((srow + i * 16) * KPITCH + sc4) * 4,
                   K + (size_t)(b * SEQ + srow + i * 16) * HID + h * DH + sc4);
    CP_COMMIT();
    __syncthreads();   // Qs visible

    // hoisted Q fragments (invariant over K tiles)
    uint32_t aq[8][4];
#pragma unroll
    for (int ks = 0; ks < 8; ks++) {
        const int kk = ks * 8;
        aq[ks][0] = Qs[ly * Q_PITCH + kk + lx];
        aq[ks][1] = Qs[(ly + 8) * Q_PITCH + kk + lx];
        aq[ks][2] = Qs[(ly + 16) * Q_PITCH + kk + lx];
        aq[ks][3] = Qs[(ly + 24) * Q_PITCH + kk + lx];
    }

    const int wn = wid * 16;

    for (int kt = 0; kt < 8; kt++) {
        const int cur = kt & 1;
        if (kt < 7) {
#pragma unroll
            for (int i = 0; i < 8; i++)
                CP_ASYNC16(kv_base + ((cur ^ 1) * KV_WORDS + (srow + i * 16) * KPITCH + sc4) * 4,
                           K + (size_t)(b * SEQ + (kt + 1) * 128 + srow + i * 16) * HID + h * DH + sc4);
            CP_COMMIT();
            CP_WAIT(1);
        } else {
            CP_WAIT(0);
        }
        __syncthreads();

        const uint32_t* KB = KVs + cur * KV_WORDS;
        float sacc[2][2][4];
#pragma unroll
        for (int mi = 0; mi < 2; mi++)
#pragma unroll
            for (int ni = 0; ni < 2; ni++)
#pragma unroll
                for (int q = 0; q < 4; q++) sacc[mi][ni][q] = 0.f;

#pragma unroll
        for (int ks = 0; ks < 8; ks++) {
            const int kk = ks * 8;
            // fragment layout note: aq[ks] packs rows {ly,+8,+16,+24}; treat as
            // two mma A-frags: {aq0,aq1,aq2',aq3'} mapping m16 rows 0..15 needs
            // regs {r(ly), r(ly+8), col+4 pair}. Rebuild proper pairs:
            uint32_t a0[4] = {aq[ks][0], aq[ks][1],
                              Qs[ly * Q_PITCH + kk + lx + 4],
                              Qs[(ly + 8) * Q_PITCH + kk + lx + 4]};
            uint32_t a1[4] = {aq[ks][2], aq[ks][3],
                              Qs[(ly + 16) * Q_PITCH + kk + lx + 4],
                              Qs[(ly + 24) * Q_PITCH + kk + lx + 4]};
            uint32_t bb[2][2];
#pragma unroll
            for (int ni = 0; ni < 2; ni++) {
                int n = wn + ni * 8;
                bb[ni][0] = KB[(n + ly) * KPITCH + kk + lx];
                bb[ni][1] = KB[(n + ly) * KPITCH + kk + lx + 4];
            }
#pragma unroll
            for (int ni = 0; ni < 2; ni++) {
                mma_tf32(sacc[0][ni], a0, bb[ni]);
                mma_tf32(sacc[1][ni], a1, bb[ni]);
            }
        }

#pragma unroll
        for (int ni = 0; ni < 2; ni++) {
            int col = kt * 128 + wn + ni * 8 + 2 * lx;
            float mk0 = mask[b * SEQ + col];
            float mk1 = mask[b * SEQ + col + 1];
#pragma unroll
            for (int mi = 0; mi < 2; mi++) {
                int row = mi * 16 + ly;
                Ssc[row * SSC_PITCH + col]           = sacc[mi][ni][0] * 0.125f + mk0;
                Ssc[row * SSC_PITCH + col + 1]       = sacc[mi][ni][1] * 0.125f + mk1;
                Ssc[(row + 8) * SSC_PITCH + col]     = sacc[mi][ni][2] * 0.125f + mk0;
                Ssc[(row + 8) * SSC_PITCH + col + 1] = sacc[mi][ni][3] * 0.125f + mk1;
            }
        }
        __syncthreads();
    }

    // ---- prefetch V tile 0 (overlaps softmax) ----
#pragma unroll
    for (int i = 0; i < 8; i++)
        CP_ASYNC16(kv_base + ((srow + i * 16) * KPITCH + sc4) * 4,
                   V + (size_t)(b * SEQ + srow + i * 16) * HID + h * DH + sc4);
    CP_COMMIT();

    // ---- softmax: one warp per row (stride 8), fast exp ----
    for (int r = wid; r < 32; r += 8) {
        float* row = Ssc + r * SSC_PITCH;
        float m = -1e30f;
        for (int c = lane; c < SEQ; c += 32) m = fmaxf(m, row[c]);
#pragma unroll
        for (int o = 16; o >= 1; o >>= 1) m = fmaxf(m, __shfl_xor_sync(0xffffffffu, m, o));
        float s = 0.f;
        for (int c = lane; c < SEQ; c += 32) {
            float e = fast_exp(row[c] - m);
            row[c] = e;
            s += e;
        }
#pragma unroll
        for (int o = 16; o >= 1; o >>= 1) s += __shfl_xor_sync(0xffffffffu, s, o);
        float inv = 1.f / s;
        for (int c = lane; c < SEQ; c += 32) row[c] *= inv;
    }
    __syncthreads();

    // ---- write probs (coalesced f4) + convert P to tf32 in place ----
    for (int i = tid; i < 8192; i += 256) {
        int row = i >> 8, c4 = (i & 255) << 2;
        float4 v = *(float4*)&Ssc[row * SSC_PITCH + c4];
        *(float4*)&probs[row * 1024 + c4] = v;
        uint4 t = {f2tf(v.x), f2tf(v.y), f2tf(v.z), f2tf(v.w)};
        *(uint4*)&Ssc[row * SSC_PITCH + c4] = t;
    }

    // ---- Phase 2: ctx = P @ V, k-split across 8 warps ----
    float cacc[2][8][4];
#pragma unroll
    for (int mi = 0; mi < 2; mi++)
#pragma unroll
        for (int ni = 0; ni < 8; ni++)
#pragma unroll
            for (int q = 0; q < 4; q++) cacc[mi][ni][q] = 0.f;

    const uint32_t* Su = (const uint32_t*)Ssc;

    for (int vt = 0; vt < 8; vt++) {
        const int cur = vt & 1;
        if (vt < 7) {
#pragma unroll
            for (int i = 0; i < 8; i++)
                CP_ASYNC16(kv_base + ((cur ^ 1) * KV_WORDS + (srow + i * 16) * KPITCH + sc4) * 4,
                           V + (size_t)(b * SEQ + (vt + 1) * 128 + srow + i * 16) * HID + h * DH + sc4);
            CP_COMMIT();
            CP_WAIT(1);
        } else {
            CP_WAIT(0);
        }
        __syncthreads();

        const uint32_t* VB = KVs + cur * KV_WORDS;
#pragma unroll
        for (int ks2 = 0; ks2 < 2; ks2++) {
            const int kloc = wid * 16 + ks2 * 8;
            const int kg = vt * 128 + kloc;
            uint32_t a[2][4], bb[8][2];
#pragma unroll
            for (int mi = 0; mi < 2; mi++) {
                int m = mi * 16;
                a[mi][0] = Su[(m + ly) * SSC_PITCH + kg + lx];
                a[mi][1] = Su[(m + ly + 8) * SSC_PITCH + kg + lx];
                a[mi][2] = Su[(m + ly) * SSC_PITCH + kg + lx + 4];
                a[mi][3] = Su[(m + ly + 8) * SSC_PITCH + kg + lx + 4];
            }
#pragma unroll
            for (int ni = 0; ni < 8; ni++) {
                bb[ni][0] = VB[(kloc + lx) * KPITCH + ni * 8 + ly];
                bb[ni][1] = VB[(kloc + lx + 4) * KPITCH + ni * 8 + ly];
            }
#pragma unroll
            for (int mi = 0; mi < 2; mi++)
#pragma unroll
                for (int ni = 0; ni < 8; ni++)
                    mma_tf32(cacc[mi][ni], a[mi], bb[ni]);
        }
        __syncthreads();
    }

    // ---- reduce partial ctx across warps via smem (KV region reused) ----
#pragma unroll
    for (int mi = 0; mi < 2; mi++)
#pragma unroll
        for (int ni = 0; ni < 8; ni++)
#pragma unroll
            for (int q = 0; q < 4; q++) {
                int row = mi * 16 + ly + (q >> 1) * 8;
                int col = ni * 8 + 2 * lx + (q & 1);
                red[wid * (32 * RED_PITCH) + row * RED_PITCH + col] = cacc[mi][ni][q];
            }
    __syncthreads();

    {
        int row = tid >> 3;
        int col = (tid & 7) << 3;
        float s[8] = {0.f, 0.f, 0.f, 0.f, 0.f, 0.f, 0.f, 0.f};
#pragma unroll
        for (int w = 0; w < 8; w++) {
            const float* rp = red + w * (32 * RED_PITCH) + row * RED_PITCH + col;
#pragma unroll
            for (int j = 0; j < 8; j++) s[j] += rp[j];
        }
        float4 v0 = {s[0], s[1], s[2], s[3]};
        float4 v1 = {s[4], s[5], s[6], s[7]};
        float* dst = ctx + (size_t)(b * SEQ + qb * 32 + row) * HID + h * DH + col;
        *(float4*)dst = v0;
        *(float4*)(dst + 4) = v1;
    }
}

// ---------------------------------------------------------------------------
extern "C" void kernel_launch(void* const* d_in, const int* in_sizes, int n_in,
                              void* d_out, int out_size) {
    (void)in_sizes; (void)n_in; (void)out_size;

    const float* m1 = (const float*)d_in[1];
    const float* m2 = (const float*)d_in[3];

    QKVArgs a;
    a.x[0] = (const float*)d_in[0];
    a.x[1] = (const float*)d_in[2];
    for (int i = 0; i < 6; i++) {
        a.w[i] = (const float*)d_in[4 + 2 * i];
        a.b[i] = (const float*)d_in[5 + 2 * i];
    }

    cudaFuncSetAttribute(qkv_gemm, cudaFuncAttributeMaxDynamicSharedMemorySize,
                         GEMM_SMEM);
    cudaFuncSetAttribute(attn_kernel, cudaFuncAttributeMaxDynamicSharedMemorySize,
                         ATTN_SMEM);

    qkv_gemm<<<dim3(16, 32, 6), 256, GEMM_SMEM>>>(a);
    attn_kernel<<<dim3(32, 16, 8), 256, ATTN_SMEM>>>(m1, m2, (float*)d_out);
}